// round 2
// baseline (speedup 1.0000x reference)
#include <cuda_runtime.h>
#include <cuda_bf16.h>
#include <math.h>

// Problem constants (from reference)
#define NNODES 50000
#define NFEAT  512
#define NHID   128
#define NCLASS 40

// Scratch (device globals: the sanctioned no-alloc workspace)
__device__ float g_xw1 [NNODES * NHID];   // x @ W1
__device__ float g_acc1[NNODES * NHID];   // spmm(x@W1)
__device__ float g_hw2 [NNODES * NCLASS]; // relu(acc1+b1) @ W2
__device__ float g_acc2[NNODES * NCLASS]; // spmm(h@W2)

// ---------------------------------------------------------------------------
// Zero the two atomic accumulators (must run every launch: graph replays)
// ---------------------------------------------------------------------------
__global__ void zero_acc_kernel() {
    const int n1 = NNODES * NHID / 4;   // float4 counts
    const int n2 = NNODES * NCLASS / 4;
    int i = blockIdx.x * blockDim.x + threadIdx.x;
    int stride = gridDim.x * blockDim.x;
    float4 z = make_float4(0.f, 0.f, 0.f, 0.f);
    for (; i < n1 + n2; i += stride) {
        if (i < n1) ((float4*)g_acc1)[i] = z;
        else        ((float4*)g_acc2)[i - n1] = z;   // FIX: rebase into g_acc2
    }
}

// ---------------------------------------------------------------------------
// GEMM1: C[M,128] = A[M,512] @ B[512,128]   (fp32, 128x128x8 tiles, 8x8/thread)
// ---------------------------------------------------------------------------
#define BM 128
#define BN 128
#define BK 8
#define TM 8
#define TN 8

__global__ __launch_bounds__(256) void sgemm1_kernel(
    const float* __restrict__ A, const float* __restrict__ B,
    float* __restrict__ C, int M)
{
    __shared__ float As[BK][BM];
    __shared__ float Bs[BK][BN];

    const int K = NFEAT;   // 512
    const int N = NHID;    // 128

    int tid = threadIdx.x;
    int block_row = blockIdx.x * BM;

    int tx = tid & 15;         // 0..15 (col tile)
    int ty = tid >> 4;         // 0..15 (row tile)

    // A tile load mapping: 128 rows x 8 k; float4 per thread
    int a_row = tid >> 1;            // 0..127
    int a_k   = (tid & 1) * 4;       // 0 or 4
    // B tile load mapping: 8 k x 128 cols; float4 per thread
    int b_k   = tid >> 5;            // 0..7
    int b_col = (tid & 31) * 4;      // 0..124

    int grow = block_row + a_row;

    float acc[TM][TN];
#pragma unroll
    for (int i = 0; i < TM; i++)
#pragma unroll
        for (int j = 0; j < TN; j++) acc[i][j] = 0.f;

    for (int k0 = 0; k0 < K; k0 += BK) {
        float4 av = (grow < M)
            ? *(const float4*)(A + (size_t)grow * K + k0 + a_k)
            : make_float4(0.f, 0.f, 0.f, 0.f);
        As[a_k + 0][a_row] = av.x;
        As[a_k + 1][a_row] = av.y;
        As[a_k + 2][a_row] = av.z;
        As[a_k + 3][a_row] = av.w;

        *(float4*)&Bs[b_k][b_col] =
            *(const float4*)(B + (size_t)(k0 + b_k) * N + b_col);

        __syncthreads();

#pragma unroll
        for (int k = 0; k < BK; k++) {
            float ar[TM], br[TN];
#pragma unroll
            for (int i = 0; i < TM; i += 4)
                *(float4*)&ar[i] = *(const float4*)&As[k][ty * TM + i];
#pragma unroll
            for (int j = 0; j < TN; j += 4)
                *(float4*)&br[j] = *(const float4*)&Bs[k][tx * TN + j];
#pragma unroll
            for (int i = 0; i < TM; i++)
#pragma unroll
                for (int j = 0; j < TN; j++)
                    acc[i][j] = fmaf(ar[i], br[j], acc[i][j]);
        }
        __syncthreads();
    }

#pragma unroll
    for (int i = 0; i < TM; i++) {
        int row = block_row + ty * TM + i;
        if (row < M) {
#pragma unroll
            for (int j = 0; j < TN; j += 4) {
                float4 v = make_float4(acc[i][j], acc[i][j + 1],
                                       acc[i][j + 2], acc[i][j + 3]);
                *(float4*)(C + (size_t)row * N + tx * TN + j) = v;
            }
        }
    }
}

// ---------------------------------------------------------------------------
// SpMM (128 feats): acc[dst] += val * feat[src]. One warp per edge,
// each lane handles one float4 chunk; vectorized L2 reduction.
// ---------------------------------------------------------------------------
__global__ void spmm128_kernel(const float* __restrict__ feat,
                               float* __restrict__ acc,
                               const int* __restrict__ es,
                               const int* __restrict__ ed,
                               const float* __restrict__ ev, int E)
{
    int t = blockIdx.x * blockDim.x + threadIdx.x;
    int e = t >> 5;
    if (e >= E) return;
    int c = t & 31;
    int s = __ldg(es + e);
    int d = __ldg(ed + e);
    float w = __ldg(ev + e);
    float4 v = *(const float4*)(feat + (size_t)s * NHID + c * 4);
    float* p = acc + (size_t)d * NHID + c * 4;
    asm volatile("red.global.v4.f32.add [%0], {%1, %2, %3, %4};"
                 :: "l"(p), "f"(v.x * w), "f"(v.y * w), "f"(v.z * w), "f"(v.w * w)
                 : "memory");
}

// ---------------------------------------------------------------------------
// SpMM (40 feats): 10 float4 chunks per edge, one per thread.
// ---------------------------------------------------------------------------
__global__ void spmm40_kernel(const float* __restrict__ feat,
                              float* __restrict__ acc,
                              const int* __restrict__ es,
                              const int* __restrict__ ed,
                              const float* __restrict__ ev, int E)
{
    int t = blockIdx.x * blockDim.x + threadIdx.x;
    int e = t / 10;
    if (e >= E) return;
    int c = t - e * 10;
    int s = __ldg(es + e);
    int d = __ldg(ed + e);
    float w = __ldg(ev + e);
    float4 v = *(const float4*)(feat + (size_t)s * NCLASS + c * 4);
    float* p = acc + (size_t)d * NCLASS + c * 4;
    asm volatile("red.global.v4.f32.add [%0], {%1, %2, %3, %4};"
                 :: "l"(p), "f"(v.x * w), "f"(v.y * w), "f"(v.z * w), "f"(v.w * w)
                 : "memory");
}

// ---------------------------------------------------------------------------
// GEMM2 with fused bias+ReLU on the operand: hw2[r,c] = relu(acc1[r,:]+b1) @ W2
// One warp per row; lane -> col lane (all 32 valid) and col lane+32 (lanes 0..7).
// ---------------------------------------------------------------------------
__global__ __launch_bounds__(256) void gemm2_kernel(
    const float* __restrict__ acc1, const float* __restrict__ b1,
    const float* __restrict__ W2, float* __restrict__ hw2, int M)
{
    int warp = (blockIdx.x * blockDim.x + threadIdx.x) >> 5;
    int lane = threadIdx.x & 31;
    if (warp >= M) return;
    const float* arow = acc1 + (size_t)warp * NHID;
    float s0 = 0.f, s1 = 0.f;
#pragma unroll 4
    for (int k = 0; k < NHID; k++) {
        float h = fmaxf(arow[k] + __ldg(b1 + k), 0.f);
        s0 = fmaf(h, __ldg(W2 + k * NCLASS + lane), s0);
        if (lane < 8)
            s1 = fmaf(h, __ldg(W2 + k * NCLASS + lane + 32), s1);
    }
    hw2[(size_t)warp * NCLASS + lane] = s0;
    if (lane < 8) hw2[(size_t)warp * NCLASS + lane + 32] = s1;
}

// ---------------------------------------------------------------------------
// Final: out = log_softmax(acc2 + b2). One warp per row of 40.
// ---------------------------------------------------------------------------
__global__ __launch_bounds__(256) void lsm_kernel(
    const float* __restrict__ acc2, const float* __restrict__ b2,
    float* __restrict__ out, int M)
{
    int warp = (blockIdx.x * blockDim.x + threadIdx.x) >> 5;
    int lane = threadIdx.x & 31;
    if (warp >= M) return;
    const float* r = acc2 + (size_t)warp * NCLASS;
    float v0 = r[lane] + __ldg(b2 + lane);
    float v1 = (lane < 8) ? (r[lane + 32] + __ldg(b2 + lane + 32)) : -INFINITY;
    float m = fmaxf(v0, v1);
#pragma unroll
    for (int o = 16; o > 0; o >>= 1)
        m = fmaxf(m, __shfl_xor_sync(0xFFFFFFFFu, m, o));
    float s = expf(v0 - m) + ((lane < 8) ? expf(v1 - m) : 0.f);
#pragma unroll
    for (int o = 16; o > 0; o >>= 1)
        s += __shfl_xor_sync(0xFFFFFFFFu, s, o);
    float lse = m + logf(s);
    out[(size_t)warp * NCLASS + lane] = v0 - lse;
    if (lane < 8) out[(size_t)warp * NCLASS + lane + 32] = v1 - lse;
}

// ---------------------------------------------------------------------------

extern "C" void kernel_launch(void* const* d_in, const int* in_sizes, int n_in,
                              void* d_out, int out_size)
{
    const float* x  = (const float*)d_in[0];
    const float* W1 = (const float*)d_in[1];
    const float* b1 = (const float*)d_in[2];
    const float* W2 = (const float*)d_in[3];
    const float* b2 = (const float*)d_in[4];
    const int*   es = (const int*)d_in[5];
    const int*   ed = (const int*)d_in[6];
    const float* ev = (const float*)d_in[7];
    int E = in_sizes[5];
    float* out = (float*)d_out;
    int M = NNODES;

    // Resolve scratch addresses every call (no static caching — harness rule).
    // cudaGetSymbolAddress is a non-stream host API; capture-safe.
    float *p_xw1, *p_acc1, *p_hw2, *p_acc2;
    cudaGetSymbolAddress((void**)&p_xw1,  g_xw1);
    cudaGetSymbolAddress((void**)&p_acc1, g_acc1);
    cudaGetSymbolAddress((void**)&p_hw2,  g_hw2);
    cudaGetSymbolAddress((void**)&p_acc2, g_acc2);

    // 1) zero atomic accumulators
    zero_acc_kernel<<<2048, 256>>>();

    // 2) xw1 = x @ W1
    sgemm1_kernel<<<(M + BM - 1) / BM, 256>>>(x, W1, p_xw1, M);

    // 3) acc1 = spmm(xw1)
    {
        long long threads = (long long)E * 32;
        int blocks = (int)((threads + 255) / 256);
        spmm128_kernel<<<blocks, 256>>>(p_xw1, p_acc1, es, ed, ev, E);
    }

    // 4) hw2 = relu(acc1 + b1) @ W2
    gemm2_kernel<<<(M * 32 + 255) / 256, 256>>>(p_acc1, b1, W2, p_hw2, M);

    // 5) acc2 = spmm(hw2)
    {
        long long threads = (long long)E * 10;
        int blocks = (int)((threads + 255) / 256);
        spmm40_kernel<<<blocks, 256>>>(p_hw2, p_acc2, es, ed, ev, E);
    }

    // 6) out = log_softmax(acc2 + b2)
    lsm_kernel<<<(M * 32 + 255) / 256, 256>>>(p_acc2, b2, out, M);
}

// round 3
// speedup vs baseline: 1.1476x; 1.1476x over previous
#include <cuda_runtime.h>
#include <cuda_bf16.h>
#include <math.h>

// Problem constants (from reference)
#define NNODES 50000
#define NFEAT  512
#define NHID   128
#define NCLASS 40

// Scratch (device globals: the sanctioned no-alloc workspace)
__device__ float g_xw1 [NNODES * NHID];   // x @ W1
__device__ float g_acc1[NNODES * NHID];   // spmm(x@W1)
__device__ float g_hw2 [NNODES * NCLASS]; // relu(acc1+b1) @ W2
__device__ float g_acc2[NNODES * NCLASS]; // spmm(h@W2)

// ---------------------------------------------------------------------------
// Packed fp32x2 FMA (sm_100+): doubles fp32 throughput per issue slot.
// ---------------------------------------------------------------------------
__device__ __forceinline__ float2 ffma2(float2 a, float2 b, float2 c) {
    unsigned long long ua = *(unsigned long long*)&a;
    unsigned long long ub = *(unsigned long long*)&b;
    unsigned long long uc = *(unsigned long long*)&c;
    unsigned long long ud;
    asm("fma.rn.f32x2 %0, %1, %2, %3;" : "=l"(ud) : "l"(ua), "l"(ub), "l"(uc));
    return *(float2*)&ud;
}

// ---------------------------------------------------------------------------
// Zero the two atomic accumulators (must run every launch: graph replays)
// ---------------------------------------------------------------------------
__global__ void zero_acc_kernel() {
    const int n1 = NNODES * NHID / 4;   // float4 counts
    const int n2 = NNODES * NCLASS / 4;
    int i = blockIdx.x * blockDim.x + threadIdx.x;
    int stride = gridDim.x * blockDim.x;
    float4 z = make_float4(0.f, 0.f, 0.f, 0.f);
    for (; i < n1 + n2; i += stride) {
        if (i < n1) ((float4*)g_acc1)[i] = z;
        else        ((float4*)g_acc2)[i - n1] = z;
    }
}

// ---------------------------------------------------------------------------
// GEMM1: C[M,128] = A[M,512] @ B[512,128]
// fp32, 128x128x8 tiles, 8x8 per thread, packed f32x2 accumulation.
// ---------------------------------------------------------------------------
#define BM 128
#define BN 128
#define BK 8
#define TM 8
#define TN 8

__global__ __launch_bounds__(256, 2) void sgemm1_kernel(
    const float* __restrict__ A, const float* __restrict__ B,
    float* __restrict__ C, int M)
{
    __shared__ float As[BK][BM];
    __shared__ float Bs[BK][BN];

    const int K = NFEAT;   // 512
    const int N = NHID;    // 128

    int tid = threadIdx.x;
    int block_row = blockIdx.x * BM;

    int tx = tid & 15;         // 0..15 (col tile)
    int ty = tid >> 4;         // 0..15 (row tile)

    int a_row = tid >> 1;            // 0..127
    int a_k   = (tid & 1) * 4;       // 0 or 4
    int b_k   = tid >> 5;            // 0..7
    int b_col = (tid & 31) * 4;      // 0..124

    int grow = block_row + a_row;

    float2 accp[TM][TN / 2];
#pragma unroll
    for (int i = 0; i < TM; i++)
#pragma unroll
        for (int j = 0; j < TN / 2; j++) accp[i][j] = make_float2(0.f, 0.f);

    for (int k0 = 0; k0 < K; k0 += BK) {
        float4 av = (grow < M)
            ? *(const float4*)(A + (size_t)grow * K + k0 + a_k)
            : make_float4(0.f, 0.f, 0.f, 0.f);
        As[a_k + 0][a_row] = av.x;
        As[a_k + 1][a_row] = av.y;
        As[a_k + 2][a_row] = av.z;
        As[a_k + 3][a_row] = av.w;

        *(float4*)&Bs[b_k][b_col] =
            *(const float4*)(B + (size_t)(k0 + b_k) * N + b_col);

        __syncthreads();

#pragma unroll
        for (int k = 0; k < BK; k++) {
            float ar[TM];
            float2 br2[TN / 2];
#pragma unroll
            for (int i = 0; i < TM; i += 4)
                *(float4*)&ar[i] = *(const float4*)&As[k][ty * TM + i];
#pragma unroll
            for (int j = 0; j < TN / 2; j += 2)
                *(float4*)&br2[j] = *(const float4*)&Bs[k][tx * TN + j * 2];
#pragma unroll
            for (int i = 0; i < TM; i++) {
                float2 a2 = make_float2(ar[i], ar[i]);
#pragma unroll
                for (int j = 0; j < TN / 2; j++)
                    accp[i][j] = ffma2(a2, br2[j], accp[i][j]);
            }
        }
        __syncthreads();
    }

#pragma unroll
    for (int i = 0; i < TM; i++) {
        int row = block_row + ty * TM + i;
        if (row < M) {
            *(float4*)(C + (size_t)row * N + tx * TN)     = *(float4*)&accp[i][0];
            *(float4*)(C + (size_t)row * N + tx * TN + 4) = *(float4*)&accp[i][2];
        }
    }
}

// ---------------------------------------------------------------------------
// SpMM (128 feats): acc[dst] += val * feat[src]. One warp per edge,
// each lane handles one float4 chunk; vectorized L2 reduction.
// ---------------------------------------------------------------------------
__global__ void spmm128_kernel(const float* __restrict__ feat,
                               float* __restrict__ acc,
                               const int* __restrict__ es,
                               const int* __restrict__ ed,
                               const float* __restrict__ ev, int E)
{
    int t = blockIdx.x * blockDim.x + threadIdx.x;
    int e = t >> 5;
    if (e >= E) return;
    int c = t & 31;
    int s = __ldg(es + e);
    int d = __ldg(ed + e);
    float w = __ldg(ev + e);
    float4 v = *(const float4*)(feat + (size_t)s * NHID + c * 4);
    float* p = acc + (size_t)d * NHID + c * 4;
    asm volatile("red.global.v4.f32.add [%0], {%1, %2, %3, %4};"
                 :: "l"(p), "f"(v.x * w), "f"(v.y * w), "f"(v.z * w), "f"(v.w * w)
                 : "memory");
}

// ---------------------------------------------------------------------------
// SpMM (40 feats): 10 float4 chunks per edge, one per thread.
// ---------------------------------------------------------------------------
__global__ void spmm40_kernel(const float* __restrict__ feat,
                              float* __restrict__ acc,
                              const int* __restrict__ es,
                              const int* __restrict__ ed,
                              const float* __restrict__ ev, int E)
{
    int t = blockIdx.x * blockDim.x + threadIdx.x;
    int e = t / 10;
    if (e >= E) return;
    int c = t - e * 10;
    int s = __ldg(es + e);
    int d = __ldg(ed + e);
    float w = __ldg(ev + e);
    float4 v = *(const float4*)(feat + (size_t)s * NCLASS + c * 4);
    float* p = acc + (size_t)d * NCLASS + c * 4;
    asm volatile("red.global.v4.f32.add [%0], {%1, %2, %3, %4};"
                 :: "l"(p), "f"(v.x * w), "f"(v.y * w), "f"(v.z * w), "f"(v.w * w)
                 : "memory");
}

// ---------------------------------------------------------------------------
// GEMM2: hw2[r,:] = relu(acc1[r,:] + b1) @ W2   (M x 128 @ 128 x 40)
// Block: 64 rows. W2 staged to smem once (20 KB, reused by all rows).
// acc1 tile staged with bias+ReLU fused at load (padded stride 129).
// Thread t: row = t>>2, cols [ (t&3)*10, +10 ).  f32x2 packed FMAs.
// ---------------------------------------------------------------------------
#define G2_ROWS 64
#define G2_APAD 129
// dynamic smem: Ws[128*40] + At[64*129]
#define G2_SMEM_FLOATS (NHID * NCLASS + G2_ROWS * G2_APAD)

__global__ __launch_bounds__(256) void gemm2_kernel(
    const float* __restrict__ acc1, const float* __restrict__ b1,
    const float* __restrict__ W2, float* __restrict__ hw2, int M)
{
    extern __shared__ float sm[];
    float* Ws = sm;                     // [128][40]
    float* At = sm + NHID * NCLASS;     // [64][129], holds relu(acc1+b1)

    int tid = threadIdx.x;
    int row0 = blockIdx.x * G2_ROWS;

    // Stage W2 (5120 floats, coalesced)
#pragma unroll
    for (int i = 0; i < NHID * NCLASS / 256; i++)
        Ws[tid + i * 256] = W2[tid + i * 256];

    // Stage A tile: 64 rows x 128 cols = 2048 float4; fuse +b1 and ReLU.
#pragma unroll
    for (int i = 0; i < G2_ROWS * NHID / (256 * 4); i++) {
        int idx4 = tid + i * 256;        // float4 index within tile
        int r    = idx4 >> 5;            // /32 float4s per row
        int c4   = idx4 & 31;
        int grow = row0 + r;
        float4 v = (grow < M)
            ? *(const float4*)(acc1 + (size_t)grow * NHID + c4 * 4)
            : make_float4(0.f, 0.f, 0.f, 0.f);
        float4 b = *(const float4*)(b1 + c4 * 4);
        float* dst = At + r * G2_APAD + c4 * 4;
        dst[0] = fmaxf(v.x + b.x, 0.f);
        dst[1] = fmaxf(v.y + b.y, 0.f);
        dst[2] = fmaxf(v.z + b.z, 0.f);
        dst[3] = fmaxf(v.w + b.w, 0.f);
    }
    __syncthreads();

    int r  = tid >> 2;          // 0..63
    int qc = (tid & 3) * 10;    // col base: 0,10,20,30

    float2 acc[5];
#pragma unroll
    for (int j = 0; j < 5; j++) acc[j] = make_float2(0.f, 0.f);

    const float* arow = At + r * G2_APAD;
#pragma unroll 8
    for (int k = 0; k < NHID; k++) {
        float h = arow[k];
        float2 h2 = make_float2(h, h);
        const float* wrow = Ws + k * NCLASS + qc;
#pragma unroll
        for (int j = 0; j < 5; j++)
            acc[j] = ffma2(h2, *(const float2*)(wrow + j * 2), acc[j]);
    }

    int grow = row0 + r;
    if (grow < M) {
        float* o = hw2 + (size_t)grow * NCLASS + qc;
#pragma unroll
        for (int j = 0; j < 5; j++)
            *(float2*)(o + j * 2) = acc[j];
    }
}

// ---------------------------------------------------------------------------
// Final: out = log_softmax(acc2 + b2). One warp per row of 40.
// ---------------------------------------------------------------------------
__global__ __launch_bounds__(256) void lsm_kernel(
    const float* __restrict__ acc2, const float* __restrict__ b2,
    float* __restrict__ out, int M)
{
    int warp = (blockIdx.x * blockDim.x + threadIdx.x) >> 5;
    int lane = threadIdx.x & 31;
    if (warp >= M) return;
    const float* r = acc2 + (size_t)warp * NCLASS;
    float v0 = r[lane] + __ldg(b2 + lane);
    float v1 = (lane < 8) ? (r[lane + 32] + __ldg(b2 + lane + 32)) : -INFINITY;
    float m = fmaxf(v0, v1);
#pragma unroll
    for (int o = 16; o > 0; o >>= 1)
        m = fmaxf(m, __shfl_xor_sync(0xFFFFFFFFu, m, o));
    float s = expf(v0 - m) + ((lane < 8) ? expf(v1 - m) : 0.f);
#pragma unroll
    for (int o = 16; o > 0; o >>= 1)
        s += __shfl_xor_sync(0xFFFFFFFFu, s, o);
    float lse = m + logf(s);
    out[(size_t)warp * NCLASS + lane] = v0 - lse;
    if (lane < 8) out[(size_t)warp * NCLASS + lane + 32] = v1 - lse;
}

// ---------------------------------------------------------------------------

extern "C" void kernel_launch(void* const* d_in, const int* in_sizes, int n_in,
                              void* d_out, int out_size)
{
    const float* x  = (const float*)d_in[0];
    const float* W1 = (const float*)d_in[1];
    const float* b1 = (const float*)d_in[2];
    const float* W2 = (const float*)d_in[3];
    const float* b2 = (const float*)d_in[4];
    const int*   es = (const int*)d_in[5];
    const int*   ed = (const int*)d_in[6];
    const float* ev = (const float*)d_in[7];
    int E = in_sizes[5];
    float* out = (float*)d_out;
    int M = NNODES;

    float *p_xw1, *p_acc1, *p_hw2, *p_acc2;
    cudaGetSymbolAddress((void**)&p_xw1,  g_xw1);
    cudaGetSymbolAddress((void**)&p_acc1, g_acc1);
    cudaGetSymbolAddress((void**)&p_hw2,  g_hw2);
    cudaGetSymbolAddress((void**)&p_acc2, g_acc2);

    // gemm2 needs 53.5 KB dynamic smem (> 48 KB default)
    const int g2_smem = G2_SMEM_FLOATS * sizeof(float);
    cudaFuncSetAttribute(gemm2_kernel,
                         cudaFuncAttributeMaxDynamicSharedMemorySize, g2_smem);

    // 1) zero atomic accumulators
    zero_acc_kernel<<<2048, 256>>>();

    // 2) xw1 = x @ W1
    sgemm1_kernel<<<(M + BM - 1) / BM, 256>>>(x, W1, p_xw1, M);

    // 3) acc1 = spmm(xw1)
    {
        long long threads = (long long)E * 32;
        int blocks = (int)((threads + 255) / 256);
        spmm128_kernel<<<blocks, 256>>>(p_xw1, p_acc1, es, ed, ev, E);
    }

    // 4) hw2 = relu(acc1 + b1) @ W2
    gemm2_kernel<<<(M + G2_ROWS - 1) / G2_ROWS, 256, g2_smem>>>(
        p_acc1, b1, W2, p_hw2, M);

    // 5) acc2 = spmm(hw2)
    {
        long long threads = (long long)E * 10;
        int blocks = (int)((threads + 255) / 256);
        spmm40_kernel<<<blocks, 256>>>(p_hw2, p_acc2, es, ed, ev, E);
    }

    // 6) out = log_softmax(acc2 + b2)
    lsm_kernel<<<(M * 32 + 255) / 256, 256>>>(p_acc2, b2, out, M);
}

// round 5
// speedup vs baseline: 1.5256x; 1.3294x over previous
#include <cuda_runtime.h>
#include <cuda_bf16.h>
#include <math.h>

// Problem constants (from reference)
#define NNODES 50000
#define NFEAT  512
#define NHID   128
#define NCLASS 40
#define MAXE   1600000

// Scratch (device globals: the sanctioned no-alloc workspace)
__device__ float g_xw1 [NNODES * NHID];   // x @ W1
__device__ float g_acc1[NNODES * NHID];   // spmm(x@W1)
__device__ float g_hw2 [NNODES * NCLASS]; // relu(acc1+b1) @ W2
__device__ float g_acc2[NNODES * NCLASS]; // spmm(h@W2)

// CSR workspace
__device__ int   g_deg [NNODES];
__device__ int   g_off [NNODES + 1];
__device__ int   g_pos [NNODES];
__device__ int   g_bsum[256];
__device__ int   g_csrc[MAXE];
__device__ float g_cw  [MAXE];

// ---------------------------------------------------------------------------
// Packed fp32x2 FMA (sm_100+)
// ---------------------------------------------------------------------------
__device__ __forceinline__ float2 ffma2(float2 a, float2 b, float2 c) {
    unsigned long long ua = *(unsigned long long*)&a;
    unsigned long long ub = *(unsigned long long*)&b;
    unsigned long long uc = *(unsigned long long*)&c;
    unsigned long long ud;
    asm("fma.rn.f32x2 %0, %1, %2, %3;" : "=l"(ud) : "l"(ua), "l"(ub), "l"(uc));
    return *(float2*)&ud;
}

// ===========================================================================
// CSR construction: zero-deg -> histogram -> 3-step scan -> scatter
// ===========================================================================
__global__ void zdeg_kernel(int n) {
    int i = blockIdx.x * blockDim.x + threadIdx.x;
    if (i < n) g_deg[i] = 0;
}

__global__ void hist_kernel(const int* __restrict__ ed, int E) {
    int e = blockIdx.x * blockDim.x + threadIdx.x;
    if (e < E) atomicAdd(&g_deg[ed[e]], 1);
}

__global__ void scan1_kernel(int n) {          // per-block inclusive scan
    __shared__ int sh[256];
    int t = threadIdx.x, i = blockIdx.x * 256 + t;
    int v = (i < n) ? g_deg[i] : 0;
    sh[t] = v; __syncthreads();
    for (int o = 1; o < 256; o <<= 1) {
        int u = (t >= o) ? sh[t - o] : 0;
        __syncthreads();
        sh[t] += u;
        __syncthreads();
    }
    if (i < n) g_off[i + 1] = sh[t];
    if (t == 255) g_bsum[blockIdx.x] = sh[255];
}

__global__ void scan2_kernel(int nb) {         // exclusive scan of block sums
    __shared__ int sh[256];
    int t = threadIdx.x;
    sh[t] = (t < nb) ? g_bsum[t] : 0; __syncthreads();
    for (int o = 1; o < 256; o <<= 1) {
        int u = (t >= o) ? sh[t - o] : 0;
        __syncthreads();
        sh[t] += u;
        __syncthreads();
    }
    int excl = (t == 0) ? 0 : sh[t - 1];
    if (t < nb) g_bsum[t] = excl;
}

__global__ void scan3_kernel(int n) {          // add block prefix; zero cursors
    int i = blockIdx.x * 256 + threadIdx.x;
    if (i < n) {
        g_off[i + 1] += g_bsum[blockIdx.x];
        g_pos[i] = 0;
    }
    if (i == 0) g_off[0] = 0;
}

__global__ void scatter_kernel(const int* __restrict__ es,
                               const int* __restrict__ ed,
                               const float* __restrict__ ev, int E) {
    int e = blockIdx.x * blockDim.x + threadIdx.x;
    if (e >= E) return;
    int d = ed[e];
    int idx = g_off[d] + atomicAdd(&g_pos[d], 1);
    g_csrc[idx] = es[e];
    g_cw[idx]   = ev[e];
}

// ---------------------------------------------------------------------------
// GEMM1: C[M,128] = A[M,512] @ B[512,128]
// fp32, 128x128x8 tiles, 8x8 per thread, packed f32x2 accumulation.
// ---------------------------------------------------------------------------
#define BM 128
#define BN 128
#define BK 8
#define TM 8
#define TN 8

__global__ __launch_bounds__(256, 2) void sgemm1_kernel(
    const float* __restrict__ A, const float* __restrict__ B,
    float* __restrict__ C, int M)
{
    __shared__ float As[BK][BM];
    __shared__ float Bs[BK][BN];

    const int K = NFEAT;
    const int N = NHID;

    int tid = threadIdx.x;
    int block_row = blockIdx.x * BM;

    int tx = tid & 15;
    int ty = tid >> 4;

    int a_row = tid >> 1;
    int a_k   = (tid & 1) * 4;
    int b_k   = tid >> 5;
    int b_col = (tid & 31) * 4;

    int grow = block_row + a_row;

    float2 accp[TM][TN / 2];
#pragma unroll
    for (int i = 0; i < TM; i++)
#pragma unroll
        for (int j = 0; j < TN / 2; j++) accp[i][j] = make_float2(0.f, 0.f);

    for (int k0 = 0; k0 < K; k0 += BK) {
        float4 av = (grow < M)
            ? *(const float4*)(A + (size_t)grow * K + k0 + a_k)
            : make_float4(0.f, 0.f, 0.f, 0.f);
        As[a_k + 0][a_row] = av.x;
        As[a_k + 1][a_row] = av.y;
        As[a_k + 2][a_row] = av.z;
        As[a_k + 3][a_row] = av.w;

        *(float4*)&Bs[b_k][b_col] =
            *(const float4*)(B + (size_t)(k0 + b_k) * N + b_col);

        __syncthreads();

#pragma unroll
        for (int k = 0; k < BK; k++) {
            float ar[TM];
            float2 br2[TN / 2];
#pragma unroll
            for (int i = 0; i < TM; i += 4)
                *(float4*)&ar[i] = *(const float4*)&As[k][ty * TM + i];
#pragma unroll
            for (int j = 0; j < TN / 2; j += 2)
                *(float4*)&br2[j] = *(const float4*)&Bs[k][tx * TN + j * 2];
#pragma unroll
            for (int i = 0; i < TM; i++) {
                float2 a2 = make_float2(ar[i], ar[i]);
#pragma unroll
                for (int j = 0; j < TN / 2; j++)
                    accp[i][j] = ffma2(a2, br2[j], accp[i][j]);
            }
        }
        __syncthreads();
    }

#pragma unroll
    for (int i = 0; i < TM; i++) {
        int row = block_row + ty * TM + i;
        if (row < M) {
            *(float4*)(C + (size_t)row * N + tx * TN)     = *(float4*)&accp[i][0];
            *(float4*)(C + (size_t)row * N + tx * TN + 4) = *(float4*)&accp[i][2];
        }
    }
}

// ---------------------------------------------------------------------------
// SpMM (128 feats) over CSR: one warp per dst row. Each lane owns one float4
// chunk; gather src rows, accumulate in registers, single write. 4x unrolled
// for MLP on the gather loads.
// ---------------------------------------------------------------------------
__global__ void spmm128_csr_kernel(const float* __restrict__ feat,
                                   float* __restrict__ out, int M)
{
    int warp = (blockIdx.x * blockDim.x + threadIdx.x) >> 5;
    int lane = threadIdx.x & 31;
    if (warp >= M) return;
    int beg = g_off[warp], end = g_off[warp + 1];

    const float* base = feat + lane * 4;
    float2 a0 = make_float2(0.f, 0.f), a1 = make_float2(0.f, 0.f);

    int j = beg;
    for (; j + 4 <= end; j += 4) {
        int   s0 = g_csrc[j],     s1 = g_csrc[j + 1];
        int   s2 = g_csrc[j + 2], s3 = g_csrc[j + 3];
        float w0 = g_cw[j],     w1 = g_cw[j + 1];
        float w2 = g_cw[j + 2], w3 = g_cw[j + 3];
        float4 v0 = *(const float4*)(base + (size_t)s0 * NHID);
        float4 v1 = *(const float4*)(base + (size_t)s1 * NHID);
        float4 v2 = *(const float4*)(base + (size_t)s2 * NHID);
        float4 v3 = *(const float4*)(base + (size_t)s3 * NHID);
        a0 = ffma2(make_float2(w0, w0), make_float2(v0.x, v0.y), a0);
        a1 = ffma2(make_float2(w0, w0), make_float2(v0.z, v0.w), a1);
        a0 = ffma2(make_float2(w1, w1), make_float2(v1.x, v1.y), a0);
        a1 = ffma2(make_float2(w1, w1), make_float2(v1.z, v1.w), a1);
        a0 = ffma2(make_float2(w2, w2), make_float2(v2.x, v2.y), a0);
        a1 = ffma2(make_float2(w2, w2), make_float2(v2.z, v2.w), a1);
        a0 = ffma2(make_float2(w3, w3), make_float2(v3.x, v3.y), a0);
        a1 = ffma2(make_float2(w3, w3), make_float2(v3.z, v3.w), a1);
    }
    for (; j < end; j++) {
        int   s = g_csrc[j];
        float w = g_cw[j];
        float4 v = *(const float4*)(base + (size_t)s * NHID);
        a0 = ffma2(make_float2(w, w), make_float2(v.x, v.y), a0);
        a1 = ffma2(make_float2(w, w), make_float2(v.z, v.w), a1);
    }

    float4 r = make_float4(a0.x, a0.y, a1.x, a1.y);
    *(float4*)(out + (size_t)warp * NHID + lane * 4) = r;
}

// ---------------------------------------------------------------------------
// SpMM (40 feats) over CSR: one half-warp (16 lanes) per dst row; lanes 0..9
// own the 10 float4 chunks. 4x unrolled.
// ---------------------------------------------------------------------------
__global__ void spmm40_csr_kernel(const float* __restrict__ feat,
                                  float* __restrict__ out, int M)
{
    int g    = (blockIdx.x * blockDim.x + threadIdx.x) >> 4;
    int l16  = threadIdx.x & 15;
    if (g >= M) return;
    int beg = g_off[g], end = g_off[g + 1];
    bool act = l16 < 10;

    const float* base = feat + l16 * 4;
    float2 a0 = make_float2(0.f, 0.f), a1 = make_float2(0.f, 0.f);
    float4 z = make_float4(0.f, 0.f, 0.f, 0.f);

    int j = beg;
    for (; j + 4 <= end; j += 4) {
        int   s0 = g_csrc[j],     s1 = g_csrc[j + 1];
        int   s2 = g_csrc[j + 2], s3 = g_csrc[j + 3];
        float w0 = g_cw[j],     w1 = g_cw[j + 1];
        float w2 = g_cw[j + 2], w3 = g_cw[j + 3];
        float4 v0 = act ? *(const float4*)(base + (size_t)s0 * NCLASS) : z;
        float4 v1 = act ? *(const float4*)(base + (size_t)s1 * NCLASS) : z;
        float4 v2 = act ? *(const float4*)(base + (size_t)s2 * NCLASS) : z;
        float4 v3 = act ? *(const float4*)(base + (size_t)s3 * NCLASS) : z;
        a0 = ffma2(make_float2(w0, w0), make_float2(v0.x, v0.y), a0);
        a1 = ffma2(make_float2(w0, w0), make_float2(v0.z, v0.w), a1);
        a0 = ffma2(make_float2(w1, w1), make_float2(v1.x, v1.y), a0);
        a1 = ffma2(make_float2(w1, w1), make_float2(v1.z, v1.w), a1);
        a0 = ffma2(make_float2(w2, w2), make_float2(v2.x, v2.y), a0);
        a1 = ffma2(make_float2(w2, w2), make_float2(v2.z, v2.w), a1);
        a0 = ffma2(make_float2(w3, w3), make_float2(v3.x, v3.y), a0);
        a1 = ffma2(make_float2(w3, w3), make_float2(v3.z, v3.w), a1);
    }
    for (; j < end; j++) {
        int   s = g_csrc[j];
        float w = g_cw[j];
        float4 v = act ? *(const float4*)(base + (size_t)s * NCLASS) : z;
        a0 = ffma2(make_float2(w, w), make_float2(v.x, v.y), a0);
        a1 = ffma2(make_float2(w, w), make_float2(v.z, v.w), a1);
    }

    if (act) {
        float4 r = make_float4(a0.x, a0.y, a1.x, a1.y);
        *(float4*)(out + (size_t)g * NCLASS + l16 * 4) = r;
    }
}

// ---------------------------------------------------------------------------
// GEMM2: hw2[r,:] = relu(acc1[r,:] + b1) @ W2   (M x 128 @ 128 x 40)
// W2 staged in smem; acc1 tile staged with fused bias+ReLU (pad 132: float4-
// aligned rows, conflict-free). Thread: 1 row x 10 cols, f32x2 FMAs.
// ---------------------------------------------------------------------------
#define G2_ROWS 64
#define G2_APAD 132
#define G2_SMEM_FLOATS (NHID * NCLASS + G2_ROWS * G2_APAD)

__global__ __launch_bounds__(256) void gemm2_kernel(
    const float* __restrict__ acc1, const float* __restrict__ b1,
    const float* __restrict__ W2, float* __restrict__ hw2, int M)
{
    extern __shared__ float sm[];
    float* Ws = sm;                     // [128][40]
    float* At = sm + NHID * NCLASS;     // [64][132]

    int tid = threadIdx.x;
    int row0 = blockIdx.x * G2_ROWS;

#pragma unroll
    for (int i = 0; i < NHID * NCLASS / 256; i++)
        Ws[tid + i * 256] = W2[tid + i * 256];

#pragma unroll
    for (int i = 0; i < G2_ROWS * NHID / (256 * 4); i++) {
        int idx4 = tid + i * 256;
        int r    = idx4 >> 5;
        int c4   = idx4 & 31;
        int grow = row0 + r;
        float4 v = (grow < M)
            ? *(const float4*)(acc1 + (size_t)grow * NHID + c4 * 4)
            : make_float4(0.f, 0.f, 0.f, 0.f);
        float4 b = *(const float4*)(b1 + c4 * 4);
        float4 h;
        h.x = fmaxf(v.x + b.x, 0.f);
        h.y = fmaxf(v.y + b.y, 0.f);
        h.z = fmaxf(v.z + b.z, 0.f);
        h.w = fmaxf(v.w + b.w, 0.f);
        *(float4*)(At + r * G2_APAD + c4 * 4) = h;
    }
    __syncthreads();

    int r  = tid >> 2;
    int qc = (tid & 3) * 10;

    float2 acc[5];
#pragma unroll
    for (int j = 0; j < 5; j++) acc[j] = make_float2(0.f, 0.f);

    const float* arow = At + r * G2_APAD;
#pragma unroll 4
    for (int k = 0; k < NHID; k += 4) {
        float4 h4 = *(const float4*)(arow + k);
#pragma unroll
        for (int kk = 0; kk < 4; kk++) {
            float h = (&h4.x)[kk];
            float2 h2 = make_float2(h, h);
            const float* wrow = Ws + (k + kk) * NCLASS + qc;
#pragma unroll
            for (int j = 0; j < 5; j++)
                acc[j] = ffma2(h2, *(const float2*)(wrow + j * 2), acc[j]);
        }
    }

    int grow = row0 + r;
    if (grow < M) {
        float* o = hw2 + (size_t)grow * NCLASS + qc;
#pragma unroll
        for (int j = 0; j < 5; j++)
            *(float2*)(o + j * 2) = acc[j];
    }
}

// ---------------------------------------------------------------------------
// Final: out = log_softmax(acc2 + b2). One warp per row of 40.
// ---------------------------------------------------------------------------
__global__ __launch_bounds__(256) void lsm_kernel(
    const float* __restrict__ acc2, const float* __restrict__ b2,
    float* __restrict__ out, int M)
{
    int warp = (blockIdx.x * blockDim.x + threadIdx.x) >> 5;
    int lane = threadIdx.x & 31;
    if (warp >= M) return;
    const float* r = acc2 + (size_t)warp * NCLASS;
    float v0 = r[lane] + __ldg(b2 + lane);
    float v1 = (lane < 8) ? (r[lane + 32] + __ldg(b2 + lane + 32)) : -INFINITY;
    float m = fmaxf(v0, v1);
#pragma unroll
    for (int o = 16; o > 0; o >>= 1)
        m = fmaxf(m, __shfl_xor_sync(0xFFFFFFFFu, m, o));
    float s = expf(v0 - m) + ((lane < 8) ? expf(v1 - m) : 0.f);
#pragma unroll
    for (int o = 16; o > 0; o >>= 1)
        s += __shfl_xor_sync(0xFFFFFFFFu, s, o);
    float lse = m + logf(s);
    out[(size_t)warp * NCLASS + lane] = v0 - lse;
    if (lane < 8) out[(size_t)warp * NCLASS + lane + 32] = v1 - lse;
}

// ---------------------------------------------------------------------------

extern "C" void kernel_launch(void* const* d_in, const int* in_sizes, int n_in,
                              void* d_out, int out_size)
{
    const float* x  = (const float*)d_in[0];
    const float* W1 = (const float*)d_in[1];
    const float* b1 = (const float*)d_in[2];
    const float* W2 = (const float*)d_in[3];
    const float* b2 = (const float*)d_in[4];
    const int*   es = (const int*)d_in[5];
    const int*   ed = (const int*)d_in[6];
    const float* ev = (const float*)d_in[7];
    int E = in_sizes[5];
    float* out = (float*)d_out;
    int M = NNODES;

    float *p_xw1, *p_acc1, *p_hw2, *p_acc2;
    cudaGetSymbolAddress((void**)&p_xw1,  g_xw1);
    cudaGetSymbolAddress((void**)&p_acc1, g_acc1);
    cudaGetSymbolAddress((void**)&p_hw2,  g_hw2);
    cudaGetSymbolAddress((void**)&p_acc2, g_acc2);

    const int g2_smem = G2_SMEM_FLOATS * sizeof(float);
    cudaFuncSetAttribute(gemm2_kernel,
                         cudaFuncAttributeMaxDynamicSharedMemorySize, g2_smem);

    int nb = (M + 255) / 256;   // 196 blocks (<=256 required by scan2)

    // --- CSR build (used by both SpMM layers) ---
    zdeg_kernel<<<nb, 256>>>(M);
    hist_kernel<<<(E + 255) / 256, 256>>>(ed, E);
    scan1_kernel<<<nb, 256>>>(M);
    scan2_kernel<<<1, 256>>>(nb);
    scan3_kernel<<<nb, 256>>>(M);
    scatter_kernel<<<(E + 255) / 256, 256>>>(es, ed, ev, E);

    // --- layer 1 ---
    sgemm1_kernel<<<(M + BM - 1) / BM, 256>>>(x, W1, p_xw1, M);
    spmm128_csr_kernel<<<(M * 32 + 255) / 256, 256>>>(p_xw1, p_acc1, M);

    // --- layer 2 ---
    gemm2_kernel<<<(M + G2_ROWS - 1) / G2_ROWS, 256, g2_smem>>>(
        p_acc1, b1, W2, p_hw2, M);
    spmm40_csr_kernel<<<(M * 16 + 255) / 256, 256>>>(p_hw2, p_acc2, M);

    // --- epilogue ---
    lsm_kernel<<<(M * 32 + 255) / 256, 256>>>(p_acc2, b2, out, M);
}